// round 4
// baseline (speedup 1.0000x reference)
#include <cuda_runtime.h>
#include <cstdint>

#define B_IMG 128
#define B_CAP 128
#define R 64
#define W 64
#define D 128

#define A_PITCH 132            // (4g + t4) distinct mod 32 -> conflict-free frag loads
#define S_PITCH 68             // float4 row loads conflict-free (4r..4r+3 spans banks)
#define TILE_F  (64 * A_PITCH) // 8448 floats per operand tile
#define SS_F    (64 * S_PITCH) // 4352 floats per sims tile

// overlays (after GEMM, As/Bs dead):
//   Ss0 = sm+0, Ss1 = sm+SS_F, SsT0 = sm+2*SS_F, SsT1 = sm+3*SS_F  (17408 < 3*TILE_F)
#define SMEM_FLOATS (3 * TILE_F + 256)
#define SMEM_BYTES  (SMEM_FLOATS * 4)   // 102400 B -> 2 CTAs/SM

__device__ __forceinline__ uint32_t f2tf32(float x) {
    uint32_t r;
    asm("cvt.rna.tf32.f32 %0, %1;" : "=r"(r) : "f"(x));
    return r;
}

#define MMA_TF32(d, a, b)                                                     \
    asm volatile(                                                             \
        "mma.sync.aligned.m16n8k8.row.col.f32.tf32.tf32.f32 "                 \
        "{%0,%1,%2,%3}, {%4,%5,%6,%7}, {%8,%9}, {%0,%1,%2,%3};\n"             \
        : "+f"(d[0]), "+f"(d[1]), "+f"(d[2]), "+f"(d[3])                      \
        : "r"(a[0]), "r"(a[1]), "r"(a[2]), "r"(a[3]), "r"(b[0]), "r"(b[1]))

// One CTA = 1 image x 2 captions. 256 threads.
__global__ __launch_bounds__(256) void select_kernel(
    const float* __restrict__ imgs, const float* __restrict__ caps,
    const int* __restrict__ img_lens, const int* __restrict__ cap_lens,
    float* __restrict__ out)
{
    extern __shared__ float sm[];
    float* As  = sm;                    // [64][A_PITCH] tf32 imgs tile
    float* Bs0 = sm + TILE_F;           // caps tile pair 0 (pair 1 at +TILE_F)
    float* red = sm + 3 * TILE_F;       // [256]

    const int i   = blockIdx.y;
    const int t0  = blockIdx.x * 2;
    const int tid = threadIdx.x;

    const int nv  = __ldg(img_lens + i);
    const int nt0 = __ldg(cap_lens + t0);
    const int nt1 = __ldg(cap_lens + t0 + 1);

    // ---- Phase 1: load + tf32-convert into padded smem ----
    {
        const float4* gi = (const float4*)(imgs + (size_t)i * R * D);
        const float4* gc = (const float4*)(caps + (size_t)t0 * W * D);
        #pragma unroll
        for (int j = tid; j < R * D / 4; j += 256) {
            float4 v = gi[j];
            int row = j >> 5, c4 = (j & 31) << 2;
            float4 w;
            w.x = __uint_as_float(f2tf32(v.x));
            w.y = __uint_as_float(f2tf32(v.y));
            w.z = __uint_as_float(f2tf32(v.z));
            w.w = __uint_as_float(f2tf32(v.w));
            *(float4*)(As + row * A_PITCH + c4) = w;
        }
        #pragma unroll
        for (int j = tid; j < 2 * W * D / 4; j += 256) {
            float4 v = gc[j];
            int p = j >> 11;
            int jj = j & 2047;
            int row = jj >> 5, c4 = (jj & 31) << 2;
            float4 w;
            w.x = __uint_as_float(f2tf32(v.x));
            w.y = __uint_as_float(f2tf32(v.y));
            w.z = __uint_as_float(f2tf32(v.z));
            w.w = __uint_as_float(f2tf32(v.w));
            *(float4*)(Bs0 + p * TILE_F + row * A_PITCH + c4) = w;
        }
    }
    __syncthreads();

    // ---- Phase 2: per pair 64x64x128 GEMM via m16n8k8 tf32 mma ----
    {
        const int warp = tid >> 5;
        const int lane = tid & 31;
        const int p    = warp >> 2;
        const int w4   = warp & 3;
        const int g    = lane >> 2;
        const int t4   = lane & 3;
        const int warpM = (w4 >> 1) * 32;
        const int warpN = (w4 & 1) * 32;
        const float* Bp = Bs0 + p * TILE_F;
        const int   ntp = p ? nt1 : nt0;

        float acc[2][4][4];
        #pragma unroll
        for (int mi = 0; mi < 2; ++mi)
            #pragma unroll
            for (int ni = 0; ni < 4; ++ni)
                #pragma unroll
                for (int q = 0; q < 4; ++q) acc[mi][ni][q] = 0.0f;

        #pragma unroll
        for (int kk = 0; kk < D; kk += 8) {
            uint32_t a[2][4], b[4][2];
            #pragma unroll
            for (int mi = 0; mi < 2; ++mi) {
                const float* ap = As + (warpM + mi * 16 + g) * A_PITCH + kk + t4;
                a[mi][0] = __float_as_uint(ap[0]);
                a[mi][1] = __float_as_uint(ap[8 * A_PITCH]);
                a[mi][2] = __float_as_uint(ap[4]);
                a[mi][3] = __float_as_uint(ap[8 * A_PITCH + 4]);
            }
            #pragma unroll
            for (int ni = 0; ni < 4; ++ni) {
                const float* bp = Bp + (warpN + ni * 8 + g) * A_PITCH + kk + t4;
                b[ni][0] = __float_as_uint(bp[0]);
                b[ni][1] = __float_as_uint(bp[4]);
            }
            #pragma unroll
            for (int mi = 0; mi < 2; ++mi)
                #pragma unroll
                for (int ni = 0; ni < 4; ++ni)
                    MMA_TF32(acc[mi][ni], a[mi], b[ni]);
        }

        __syncthreads();   // operands dead; sims tiles overlay As/Bs

        float* Sp  = sm + p * SS_F;            // row-major  [region][word]
        float* SpT = sm + 2 * SS_F + p * SS_F; // transposed [word][region]
        #pragma unroll
        for (int mi = 0; mi < 2; ++mi) {
            #pragma unroll
            for (int ni = 0; ni < 4; ++ni) {
                int r0 = warpM + mi * 16 + g;
                int r1 = r0 + 8;
                int c0 = warpN + ni * 8 + 2 * t4;
                bool cv0 = (c0 < ntp), cv1 = (c0 + 1 < ntp);
                float v00 = (r0 < nv && cv0) ? acc[mi][ni][0] : -1.0f;
                float v01 = (r0 < nv && cv1) ? acc[mi][ni][1] : -1.0f;
                float v10 = (r1 < nv && cv0) ? acc[mi][ni][2] : -1.0f;
                float v11 = (r1 < nv && cv1) ? acc[mi][ni][3] : -1.0f;
                *(float2*)(Sp + r0 * S_PITCH + c0) = make_float2(v00, v01);
                *(float2*)(Sp + r1 * S_PITCH + c0) = make_float2(v10, v11);
                SpT[c0 * S_PITCH + r0]       = v00;
                SpT[(c0 + 1) * S_PITCH + r0] = v01;
                SpT[c0 * S_PITCH + r1]       = v10;
                SpT[(c0 + 1) * S_PITCH + r1] = v11;
            }
        }
    }
    __syncthreads();

    // ---- Phase 3: sparsemax, shifted-accumulator Michelot ----
    // tid layout: [pair(1)][role(1)][r(6)]; role 0 = region rows, role 1 = word rows
    {
        const int p    = tid >> 7;
        const int role = (tid >> 6) & 1;
        const int r    = tid & 63;
        const int ntp  = p ? nt1 : nt0;
        const int m    = role ? nv : ntp;       // valid elements in this row
        const float* base = sm + (role ? 2 * SS_F : 0) + p * SS_F + r * S_PITCH;

        // load + shift: z' = z + 256 (masked entries become exactly 255)
        float z[64];
        const float4* zp = (const float4*)base;
        #pragma unroll
        for (int j = 0; j < 16; ++j) {
            float4 v = zp[j];
            z[4 * j]     = v.x + 256.0f;
            z[4 * j + 1] = v.y + 256.0f;
            z[4 * j + 2] = v.z + 256.0f;
            z[4 * j + 3] = v.w + 256.0f;
        }

        // total shifted sum
        float s0 = 0.f, s1 = 0.f, s2 = 0.f, s3 = 0.f;
        #pragma unroll
        for (int j = 0; j < 64; j += 4) {
            s0 += z[j]; s1 += z[j + 1]; s2 += z[j + 2]; s3 += z[j + 3];
        }
        const float S = (s0 + s1) + (s2 + s3);

        // analytic init: support = valid set (masked are exactly 255 shifted)
        float kprev = (float)m;
        float tau = __fdividef(S - (float)(64 - m) * 255.0f - 1.0f, kprev);
        if (!(tau > 255.0f)) {                  // rare: true support includes masked
            tau = (S - 1.0f) * (1.0f / 64.0f);
            kprev = 64.0f;
        }

        // Michelot: q = sum+256*count jointly; tau' = (q-1)/k
        float qf = 0.0f, kf = kprev;
        #pragma unroll 1
        for (int it = 0; it < 24; ++it) {
            float q0 = 0.f, q1 = 0.f, q2 = 0.f, q3 = 0.f;
            #pragma unroll
            for (int j = 0; j < 64; j += 4) {
                if (z[j]     > tau) q0 += z[j];
                if (z[j + 1] > tau) q1 += z[j + 1];
                if (z[j + 2] > tau) q2 += z[j + 2];
                if (z[j + 3] > tau) q3 += z[j + 3];
            }
            qf = (q0 + q1) + (q2 + q3);
            kf = rintf(qf * 0.00390625f);       // count = rint(q/256)
            float ntau = __fdividef(qf - 1.0f, kf);
            if (kf == kprev) break;             // support stable -> fixpoint
            kprev = kf;
            tau = ntau;
        }

        // rsum = sum_active (z-tau)*z = sum relu(z'-tau')^2 + (tau'-256)*sum relu
        float a0 = 0.f, a1 = 0.f, a2 = 0.f, a3 = 0.f;
        #pragma unroll
        for (int j = 0; j < 64; j += 4) {
            float p0 = fmaxf(z[j]     - tau, 0.f);
            float p1 = fmaxf(z[j + 1] - tau, 0.f);
            float p2 = fmaxf(z[j + 2] - tau, 0.f);
            float p3 = fmaxf(z[j + 3] - tau, 0.f);
            a0 = fmaf(p0, p0, a0);
            a1 = fmaf(p1, p1, a1);
            a2 = fmaf(p2, p2, a2);
            a3 = fmaf(p3, p3, a3);
        }
        float sp   = qf - kf * tau;             // sum of p over support
        float rsum = ((a0 + a1) + (a2 + a3)) + (tau - 256.0f) * sp;

        bool valid = role ? (r < ntp) : (r < nv);
        red[tid] = valid ? rsum : 0.0f;
    }
    __syncthreads();

    // ---- Phase 4: masked means; warp 0 -> pair 0, warp 1 -> pair 1 ----
    if (tid < 64) {
        const int wp   = tid >> 5;
        const int lane = tid & 31;
        const float* rp = red + wp * 128;
        float v = rp[lane]      + rp[lane + 32];
        float w = rp[64 + lane] + rp[96 + lane];
        #pragma unroll
        for (int o = 16; o; o >>= 1) {
            v += __shfl_down_sync(0xffffffffu, v, o);
            w += __shfl_down_sync(0xffffffffu, w, o);
        }
        if (lane == 0) {
            int nt = wp ? nt1 : nt0;
            out[i * B_CAP + t0 + wp] = 0.5f * (v / (float)nv + w / (float)nt);
        }
    }
}

extern "C" void kernel_launch(void* const* d_in, const int* in_sizes, int n_in,
                              void* d_out, int out_size)
{
    // metadata order: img_cls, imgs, cap_cls, caps, img_lens, cap_lens
    const float* imgs     = (const float*)d_in[1];
    const float* caps     = (const float*)d_in[3];
    const int*   img_lens = (const int*)d_in[4];
    const int*   cap_lens = (const int*)d_in[5];
    float*       out      = (float*)d_out;

    cudaFuncSetAttribute(select_kernel,
                         cudaFuncAttributeMaxDynamicSharedMemorySize, SMEM_BYTES);

    dim3 grid(B_CAP / 2, B_IMG);
    select_kernel<<<grid, 256, SMEM_BYTES>>>(imgs, caps, img_lens, cap_lens, out);
}

// round 5
// speedup vs baseline: 1.4547x; 1.4547x over previous
#include <cuda_runtime.h>
#include <cstdint>

#define B_IMG 128
#define B_CAP 128
#define R 64
#define W 64
#define D 128

#define A_PITCH 132            // (4g + t4) distinct mod 32 -> conflict-free frag loads
#define S_PITCH 65             // stride 1 across threads -> conflict-free rows AND cols
#define TILE_F  (64 * A_PITCH) // 8448 floats per operand tile
#define SS_F    (64 * S_PITCH) // 4160 floats per sims tile (2 overlay into As: 8320<=8448)

#define SMEM_FLOATS (3 * TILE_F + 256)
#define SMEM_BYTES  (SMEM_FLOATS * 4)   // 100 KB -> 2 CTAs/SM

__device__ __forceinline__ uint32_t f2tf32(float x) {
    uint32_t r;
    asm("cvt.rna.tf32.f32 %0, %1;" : "=r"(r) : "f"(x));
    return r;
}

#define MMA_TF32(d, a, b)                                                     \
    asm volatile(                                                             \
        "mma.sync.aligned.m16n8k8.row.col.f32.tf32.tf32.f32 "                 \
        "{%0,%1,%2,%3}, {%4,%5,%6,%7}, {%8,%9}, {%0,%1,%2,%3};\n"             \
        : "+f"(d[0]), "+f"(d[1]), "+f"(d[2]), "+f"(d[3])                      \
        : "r"(a[0]), "r"(a[1]), "r"(a[2]), "r"(a[3]), "r"(b[0]), "r"(b[1]))

// One CTA = 1 image x 2 captions. 256 threads.
// Warps 0-3 -> pair 0 GEMM, warps 4-7 -> pair 1 GEMM (each warp 32x32 of 64x64).
__global__ __launch_bounds__(256) void select_kernel(
    const float* __restrict__ imgs, const float* __restrict__ caps,
    const int* __restrict__ img_lens, const int* __restrict__ cap_lens,
    float* __restrict__ out)
{
    extern __shared__ float sm[];
    float* As  = sm;                    // [64][A_PITCH] tf32 imgs tile
    float* Bs0 = sm + TILE_F;           // caps tile pair 0 (pair 1 at +TILE_F)
    float* red = sm + 3 * TILE_F;       // [256]

    const int i   = blockIdx.y;
    const int t0  = blockIdx.x * 2;
    const int tid = threadIdx.x;

    const int nv  = __ldg(img_lens + i);
    const int nt0 = __ldg(cap_lens + t0);
    const int nt1 = __ldg(cap_lens + t0 + 1);

    // ---- Phase 1: load + tf32-convert into padded smem ----
    {
        const float4* gi = (const float4*)(imgs + (size_t)i * R * D);
        const float4* gc = (const float4*)(caps + (size_t)t0 * W * D);
        #pragma unroll
        for (int j = tid; j < R * D / 4; j += 256) {
            float4 v = gi[j];
            int row = j >> 5, c4 = (j & 31) << 2;
            float4 w;
            w.x = __uint_as_float(f2tf32(v.x));
            w.y = __uint_as_float(f2tf32(v.y));
            w.z = __uint_as_float(f2tf32(v.z));
            w.w = __uint_as_float(f2tf32(v.w));
            *(float4*)(As + row * A_PITCH + c4) = w;
        }
        #pragma unroll
        for (int j = tid; j < 2 * W * D / 4; j += 256) {
            float4 v = gc[j];
            int p = j >> 11;
            int jj = j & 2047;
            int row = jj >> 5, c4 = (jj & 31) << 2;
            float4 w;
            w.x = __uint_as_float(f2tf32(v.x));
            w.y = __uint_as_float(f2tf32(v.y));
            w.z = __uint_as_float(f2tf32(v.z));
            w.w = __uint_as_float(f2tf32(v.w));
            *(float4*)(Bs0 + p * TILE_F + row * A_PITCH + c4) = w;
        }
    }
    __syncthreads();

    // ---- Phase 2: per pair 64x64x128 GEMM via m16n8k8 tf32 mma ----
    {
        const int warp = tid >> 5;
        const int lane = tid & 31;
        const int p    = warp >> 2;
        const int w4   = warp & 3;
        const int g    = lane >> 2;
        const int t4   = lane & 3;
        const int warpM = (w4 >> 1) * 32;
        const int warpN = (w4 & 1) * 32;
        const float* Bp = Bs0 + p * TILE_F;
        const int   ntp = p ? nt1 : nt0;

        float acc[2][4][4];
        #pragma unroll
        for (int mi = 0; mi < 2; ++mi)
            #pragma unroll
            for (int ni = 0; ni < 4; ++ni)
                #pragma unroll
                for (int q = 0; q < 4; ++q) acc[mi][ni][q] = 0.0f;

        #pragma unroll
        for (int kk = 0; kk < D; kk += 8) {
            uint32_t a[2][4], b[4][2];
            #pragma unroll
            for (int mi = 0; mi < 2; ++mi) {
                const float* ap = As + (warpM + mi * 16 + g) * A_PITCH + kk + t4;
                a[mi][0] = __float_as_uint(ap[0]);
                a[mi][1] = __float_as_uint(ap[8 * A_PITCH]);
                a[mi][2] = __float_as_uint(ap[4]);
                a[mi][3] = __float_as_uint(ap[8 * A_PITCH + 4]);
            }
            #pragma unroll
            for (int ni = 0; ni < 4; ++ni) {
                const float* bp = Bp + (warpN + ni * 8 + g) * A_PITCH + kk + t4;
                b[ni][0] = __float_as_uint(bp[0]);
                b[ni][1] = __float_as_uint(bp[4]);
            }
            #pragma unroll
            for (int mi = 0; mi < 2; ++mi)
                #pragma unroll
                for (int ni = 0; ni < 4; ++ni)
                    MMA_TF32(acc[mi][ni], a[mi], b[ni]);
        }

        __syncthreads();   // all warps done reading As/Bs; Ss overlays As

        float* Sp = sm + p * SS_F;
        #pragma unroll
        for (int mi = 0; mi < 2; ++mi) {
            #pragma unroll
            for (int ni = 0; ni < 4; ++ni) {
                int r0 = warpM + mi * 16 + g;
                int r1 = r0 + 8;
                int c0 = warpN + ni * 8 + 2 * t4;
                bool cv0 = (c0 < ntp), cv1 = (c0 + 1 < ntp);
                Sp[r0 * S_PITCH + c0]     = (r0 < nv && cv0) ? acc[mi][ni][0] : -1.0f;
                Sp[r0 * S_PITCH + c0 + 1] = (r0 < nv && cv1) ? acc[mi][ni][1] : -1.0f;
                Sp[r1 * S_PITCH + c0]     = (r1 < nv && cv0) ? acc[mi][ni][2] : -1.0f;
                Sp[r1 * S_PITCH + c0 + 1] = (r1 < nv && cv1) ? acc[mi][ni][3] : -1.0f;
            }
        }
    }
    __syncthreads();

    // ---- Phase 3: sparsemax, shifted-accumulator Michelot ----
    // tid layout: [pair(1)][role(1)][r(6)]; role 0 = region rows, role 1 = word cols
    {
        const int p    = tid >> 7;
        const int role = (tid >> 6) & 1;
        const int r    = tid & 63;
        const float* Sp = sm + p * SS_F;
        const int   ntp = p ? nt1 : nt0;
        const int   m   = role ? nv : ntp;      // valid elements in this line

        const float* bp = role ? (Sp + r) : (Sp + r * S_PITCH);
        const int   str = role ? S_PITCH : 1;

        // load + shift: z' = z + 256 (masked entries become exactly 255.0f)
        float z[64];
        #pragma unroll
        for (int j = 0; j < 64; ++j) z[j] = bp[j * str] + 256.0f;

        float s0 = 0.f, s1 = 0.f, s2 = 0.f, s3 = 0.f;
        #pragma unroll
        for (int j = 0; j < 64; j += 4) {
            s0 += z[j]; s1 += z[j + 1]; s2 += z[j + 2]; s3 += z[j + 3];
        }
        const float S = (s0 + s1) + (s2 + s3);

        // analytic init: support = valid set (masked entries sit at exactly 255)
        float kprev = (float)m;
        float tau = __fdividef(S - (float)(64 - m) * 255.0f - 1.0f, kprev);
        if (!(tau > 255.0f)) {                  // rare: true support includes masked
            tau = (S - 1.0f) * (1.0f / 64.0f);
            kprev = 64.0f;
        }

        // Michelot with joint sum+count accumulator: q = sum + 256*count
        float qf = kprev * tau + 1.0f;          // consistent q for the init tau
        float kf = kprev;
        #pragma unroll 1
        for (int it = 0; it < 24; ++it) {
            float q0 = 0.f, q1 = 0.f, q2 = 0.f, q3 = 0.f;
            #pragma unroll
            for (int j = 0; j < 64; j += 4) {
                if (z[j]     > tau) q0 += z[j];
                if (z[j + 1] > tau) q1 += z[j + 1];
                if (z[j + 2] > tau) q2 += z[j + 2];
                if (z[j + 3] > tau) q3 += z[j + 3];
            }
            qf = (q0 + q1) + (q2 + q3);
            kf = rintf(qf * 0.00390625f);       // exact count: |sum sims| <= 64 < 128
            if (kf == kprev) break;             // support stable -> tau is the fixpoint
            kprev = kf;
            tau = __fdividef(qf - 1.0f, kf);
        }

        // rsum = sum_active (z - tau)*z  [unshifted]
        //      = sum relu(z'-tau')^2 + (tau'-256) * sum relu(z'-tau')
        float a0 = 0.f, a1 = 0.f, a2 = 0.f, a3 = 0.f;
        #pragma unroll
        for (int j = 0; j < 64; j += 4) {
            float p0 = fmaxf(z[j]     - tau, 0.f);
            float p1 = fmaxf(z[j + 1] - tau, 0.f);
            float p2 = fmaxf(z[j + 2] - tau, 0.f);
            float p3 = fmaxf(z[j + 3] - tau, 0.f);
            a0 = fmaf(p0, p0, a0);
            a1 = fmaf(p1, p1, a1);
            a2 = fmaf(p2, p2, a2);
            a3 = fmaf(p3, p3, a3);
        }
        float sp   = qf - kf * tau;             // sum of (z'-tau') over support
        float rsum = ((a0 + a1) + (a2 + a3)) + (tau - 256.0f) * sp;

        bool valid = role ? (r < ntp) : (r < nv);
        red[tid] = valid ? rsum : 0.0f;
    }
    __syncthreads();

    // ---- Phase 4: masked means; warp 0 -> pair 0, warp 1 -> pair 1 ----
    if (tid < 64) {
        const int wp   = tid >> 5;
        const int lane = tid & 31;
        const float* rp = red + wp * 128;
        float v = rp[lane]      + rp[lane + 32];
        float w = rp[64 + lane] + rp[96 + lane];
        #pragma unroll
        for (int o = 16; o; o >>= 1) {
            v += __shfl_down_sync(0xffffffffu, v, o);
            w += __shfl_down_sync(0xffffffffu, w, o);
        }
        if (lane == 0) {
            int nt = wp ? nt1 : nt0;
            out[i * B_CAP + t0 + wp] = 0.5f * (v / (float)nv + w / (float)nt);
        }
    }
}

extern "C" void kernel_launch(void* const* d_in, const int* in_sizes, int n_in,
                              void* d_out, int out_size)
{
    // metadata order: img_cls, imgs, cap_cls, caps, img_lens, cap_lens
    const float* imgs     = (const float*)d_in[1];
    const float* caps     = (const float*)d_in[3];
    const int*   img_lens = (const int*)d_in[4];
    const int*   cap_lens = (const int*)d_in[5];
    float*       out      = (float*)d_out;

    cudaFuncSetAttribute(select_kernel,
                         cudaFuncAttributeMaxDynamicSharedMemorySize, SMEM_BYTES);

    dim3 grid(B_CAP / 2, B_IMG);
    select_kernel<<<grid, 256, SMEM_BYTES>>>(imgs, caps, img_lens, cap_lens, out);
}